// round 2
// baseline (speedup 1.0000x reference)
#include <cuda_runtime.h>

typedef unsigned long long u64;

// ---- packed f32x2 helpers (Blackwell sm_100a) ----
__device__ __forceinline__ u64 pk2(float lo, float hi) {
    u64 r; asm("mov.b64 %0, {%1, %2};" : "=l"(r) : "f"(lo), "f"(hi)); return r;
}
__device__ __forceinline__ void upk2(u64 v, float& lo, float& hi) {
    asm("mov.b64 {%0, %1}, %2;" : "=f"(lo), "=f"(hi) : "l"(v));
}
__device__ __forceinline__ u64 fma2(u64 a, u64 b, u64 c) {
    u64 r; asm("fma.rn.f32x2 %0, %1, %2, %3;" : "=l"(r) : "l"(a), "l"(b), "l"(c)); return r;
}
__device__ __forceinline__ u64 mul2(u64 a, u64 b) {
    u64 r; asm("mul.rn.f32x2 %0, %1, %2;" : "=l"(r) : "l"(a), "l"(b)); return r;
}

// compile-time-foldable popcount / adjacent-pair parity for 5-bit values
#define PC5(v) ((((v)>>0)&1)+(((v)>>1)&1)+(((v)>>2)&1)+(((v)>>3)&1)+(((v)>>4)&1))
#define ADJ5(v) (PC5((v)&((v)>>1)) & 1)

// Wire w of the 10-qubit register = flat-index bit (9-w).
// lane bit u (u=0..4)  -> global bit 5+u -> wire 4-u
// local bit v (v=0..4) -> global bit v   -> wire 9-v

__global__ __launch_bounds__(128)
void qsim_kernel(const float* __restrict__ x,
                 const float* __restrict__ params,
                 const float* __restrict__ w_cls,
                 const float* __restrict__ b_cls,
                 float* __restrict__ out, int B)
{
    __shared__ float cp[64], sp[64], wsh[160], bsh[16];
    const int tid = threadIdx.x;
    if (tid < 60) {
        float s, c;
        sincosf(params[tid] * 0.5f, &s, &c);
        sp[tid] = s; cp[tid] = c;
    }
    for (int k = tid; k < 160; k += 128) wsh[k] = w_cls[k];
    if (tid < 16) bsh[tid] = b_cls[tid];
    __syncthreads();

    const int lane = tid & 31;
    const int elem = blockIdx.x * (blockDim.x >> 5) + (tid >> 5);
    if (elem >= B) return;

    // ---------- initial product state from RX layer ----------
    float cx[10], sx[10];
#pragma unroll
    for (int q = 0; q < 10; q++) {
        float xv = x[elem * 10 + q];
        sincosf(xv * 0.5f, &sx[q], &cx[q]);
    }
    // product over lane bits (wires 4..0)
    float lp = 1.0f;
#pragma unroll
    for (int u = 0; u < 5; u++)
        lp *= ((lane >> u) & 1) ? sx[4 - u] : cx[4 - u];

    // phase (-i)^k, k = popc(lane)+popc(i); precompute 4 packed phase regs
    const int pl = __popc(lane);
    u64 ph[4];
#pragma unroll
    for (int j = 0; j < 4; j++) {
        int k = (pl + j) & 3;
        float pr = (k == 0) ? 1.0f : ((k == 2) ? -1.0f : 0.0f);
        float pi = (k == 1) ? -1.0f : ((k == 3) ? 1.0f : 0.0f);
        ph[j] = pk2(pr, pi);
    }

    u64 st[32];
#pragma unroll
    for (int i = 0; i < 32; i++) {
        float r = lp;
#pragma unroll
        for (int v = 0; v < 5; v++)
            r *= ((i >> v) & 1) ? sx[9 - v] : cx[9 - v];
        st[i] = mul2(pk2(r, r), ph[PC5(i) & 3]);
    }

    // ---------- CZ sign constants ----------
    // flip(b) = sig_lane ^ sig_local(i) ^ (bit5(lane) & bit4(i))
    const int sig_lane = ADJ5(lane);
    const int laneb0   = lane & 1;              // global bit 5
    const float fa = sig_lane ? -1.0f : 1.0f;
    const float fb = (sig_lane ^ laneb0) ? -1.0f : 1.0f;
    const u64 PA  = pk2( fa,  fa), PAn = pk2(-fa, -fa);
    const u64 PB  = pk2( fb,  fb), PBn = pk2(-fb, -fb);

    // ---------- 6 variational layers ----------
#pragma unroll 1
    for (int d = 0; d < 6; d++) {
        const float* cpd = cp + d * 10;
        const float* spd = sp + d * 10;

        // wires 0..4: cross-lane gates (lane bit u = 4-q)
#pragma unroll
        for (int q = 0; q < 5; q++) {
            const float c = cpd[q], s = spd[q];
            const int u = 4 - q;
            // bit==0 side: n0 = c*a0 - s*a1 ; bit==1 side: n1 = s*a0 + c*a1
            const float se = ((lane >> u) & 1) ? s : -s;
            const u64 cc = pk2(c, c), sse = pk2(se, se);
#pragma unroll
            for (int i = 0; i < 32; i++) {
                u64 other = __shfl_xor_sync(0xffffffffu, st[i], 1 << u);
                st[i] = fma2(cc, st[i], mul2(sse, other));
            }
        }

        // wires 5..9: in-register gates (local bit v = 9-q)
#pragma unroll
        for (int q = 5; q < 10; q++) {
            const float c = cpd[q], s = spd[q];
            const int v = 9 - q;
            const u64 cc = pk2(c, c), ss = pk2(s, s), nss = pk2(-s, -s);
#pragma unroll
            for (int t = 0; t < 16; t++) {
                const int i = ((t >> v) << (v + 1)) | (t & ((1 << v) - 1));
                const int j = i | (1 << v);
                u64 a0 = st[i], a1 = st[j];
                st[i] = fma2(cc, a0, mul2(nss, a1));  // c*a0 - s*a1
                st[j] = fma2(cc, a1, mul2(ss,  a0));  // s*a0 + c*a1
            }
        }

        // CZ chain; last layer's CZ doesn't affect |amp|^2 -> skip
        if (d < 5) {
#pragma unroll
            for (int i = 0; i < 32; i++) {
                const u64 m = (i >= 16) ? (ADJ5(i) ? PBn : PB)
                                        : (ADJ5(i) ? PAn : PA);
                st[i] = mul2(st[i], m);
            }
        }
    }

    // ---------- probabilities and <Z_q> ----------
    float t_all = 0.0f, tb0 = 0, tb1 = 0, tb2 = 0, tb3 = 0, tb4 = 0;
#pragma unroll
    for (int i = 0; i < 32; i++) {
        float re, im; upk2(st[i], re, im);
        float p = fmaf(im, im, re * re);
        t_all += p;
        if (i & 1)  tb0 += p;
        if (i & 2)  tb1 += p;
        if (i & 4)  tb2 += p;
        if (i & 8)  tb3 += p;
        if (i & 16) tb4 += p;
    }
    float ex[10];
#pragma unroll
    for (int q = 0; q < 5; q++) {
        const int u = 4 - q;
        ex[q] = ((lane >> u) & 1) ? -t_all : t_all;
    }
    ex[5] = t_all - 2.0f * tb4;  // wire 5 -> local bit 4
    ex[6] = t_all - 2.0f * tb3;
    ex[7] = t_all - 2.0f * tb2;
    ex[8] = t_all - 2.0f * tb1;
    ex[9] = t_all - 2.0f * tb0;

#pragma unroll
    for (int m = 16; m >= 1; m >>= 1) {
#pragma unroll
        for (int q = 0; q < 10; q++)
            ex[q] += __shfl_xor_sync(0xffffffffu, ex[q], m);
    }

    // ---------- classifier head: lanes 0..15 emit one class each ----------
    if (lane < 16) {
        float acc = bsh[lane];
#pragma unroll
        for (int q = 0; q < 10; q++)
            acc = fmaf(ex[q], wsh[lane * 10 + q], acc);
        out[elem * 16 + lane] = acc;
    }
}

extern "C" void kernel_launch(void* const* d_in, const int* in_sizes, int n_in,
                              void* d_out, int out_size)
{
    const float* x      = (const float*)d_in[0];  // (B, 10)
    const float* params = (const float*)d_in[1];  // (6, 10)
    const float* w_cls  = (const float*)d_in[2];  // (16, 10)
    const float* b_cls  = (const float*)d_in[3];  // (16,)
    float* out = (float*)d_out;

    const int B = in_sizes[0] / 10;
    const int warps_per_block = 4;
    const int blocks = (B + warps_per_block - 1) / warps_per_block;
    qsim_kernel<<<blocks, warps_per_block * 32>>>(x, params, w_cls, b_cls, out, B);
}

// round 3
// speedup vs baseline: 1.1931x; 1.1931x over previous
#include <cuda_runtime.h>

typedef unsigned long long u64;

// ---- packed f32x2 helpers (Blackwell sm_100a) ----
__device__ __forceinline__ u64 pk2(float lo, float hi) {
    u64 r; asm("mov.b64 %0, {%1, %2};" : "=l"(r) : "f"(lo), "f"(hi)); return r;
}
__device__ __forceinline__ void upk2(u64 v, float& lo, float& hi) {
    asm("mov.b64 {%0, %1}, %2;" : "=f"(lo), "=f"(hi) : "l"(v));
}
__device__ __forceinline__ u64 fma2(u64 a, u64 b, u64 c) {
    u64 r; asm("fma.rn.f32x2 %0, %1, %2, %3;" : "=l"(r) : "l"(a), "l"(b), "l"(c)); return r;
}
__device__ __forceinline__ u64 mul2(u64 a, u64 b) {
    u64 r; asm("mul.rn.f32x2 %0, %1, %2;" : "=l"(r) : "l"(a), "l"(b)); return r;
}

#define PC5(v) ((((v)>>0)&1)+(((v)>>1)&1)+(((v)>>2)&1)+(((v)>>3)&1)+(((v)>>4)&1))
#define ADJ5(v) (PC5((v)&((v)>>1)) & 1)

// Wire w of the 10-qubit register = flat-index bit (9-w).
// lane bit u (u=0..4)  -> global bit 5+u -> wire 4-u
// local bit v (v=0..4) -> global bit v   -> wire 9-v

__global__ __launch_bounds__(128)
void qsim_kernel(const float* __restrict__ x,
                 const float* __restrict__ params,
                 const float* __restrict__ w_cls,
                 const float* __restrict__ b_cls,
                 float* __restrict__ out, int B)
{
    __shared__ float tsh[64], cwork[64], wsh[160], bsh[16];
    __shared__ float Cprod_sh;
    const int tid = threadIdx.x;
    if (tid < 60) {
        float s, c;
        sincosf(params[tid] * 0.5f, &s, &c);
        tsh[tid] = s / c;       // tan(theta/2)
        cwork[tid] = c;
    }
    for (int k = tid; k < 160; k += 128) wsh[k] = w_cls[k];
    if (tid < 16) bsh[tid] = b_cls[tid];
    __syncthreads();
    if (tid == 0) {
        float p = 1.0f;
        for (int k = 0; k < 60; k++) p *= cwork[k];
        Cprod_sh = p;           // amplitudes scale; probs get p^2 automatically
    }
    __syncthreads();
    const float Cprod = Cprod_sh;

    const int lane = tid & 31;
    const int elem = blockIdx.x * (blockDim.x >> 5) + (tid >> 5);
    if (elem >= B) return;

    // ---------- initial product state from RX layer ----------
    float cx[10], sx[10];
#pragma unroll
    for (int q = 0; q < 10; q++) {
        float xv = x[elem * 10 + q];
        sincosf(xv * 0.5f, &sx[q], &cx[q]);
    }
    // product over lane bits (wires 4..0), with deferred-cos scale folded in
    float lp = Cprod;
#pragma unroll
    for (int u = 0; u < 5; u++)
        lp *= ((lane >> u) & 1) ? sx[4 - u] : cx[4 - u];

    // recursive product over local bits: pr[i] = lp * prod_v (bit? sx : cx)[9-v]
    float pr[32];
    pr[0] = lp;
#pragma unroll
    for (int v = 0; v < 5; v++) {
#pragma unroll
        for (int i = 0; i < 16; i++) {
            if (i < (1 << v)) {
                pr[i | (1 << v)] = pr[i] * sx[9 - v];
                pr[i]            = pr[i] * cx[9 - v];
            }
        }
    }

    // phase (-i)^k, k = popc(lane)+popc(i)
    const int pl = __popc(lane);
    u64 ph[4];
#pragma unroll
    for (int j = 0; j < 4; j++) {
        int k = (pl + j) & 3;
        float prr = (k == 0) ? 1.0f : ((k == 2) ? -1.0f : 0.0f);
        float pii = (k == 1) ? -1.0f : ((k == 3) ? 1.0f : 0.0f);
        ph[j] = pk2(prr, pii);
    }

    u64 st[32];
#pragma unroll
    for (int i = 0; i < 32; i++)
        st[i] = mul2(pk2(pr[i], pr[i]), ph[PC5(i) & 3]);

    // ---------- CZ sign masks (XOR on sign bits, ALU pipe) ----------
    const u64 NEG = 0x8000000080000000ull;
    const int sig_lane = ADJ5(lane);
    const int laneb0   = lane & 1;              // global bit 5
    const u64 SA  = sig_lane ? NEG : 0ull;
    const u64 SB  = (sig_lane ^ laneb0) ? NEG : 0ull;
    const u64 SAn = SA ^ NEG, SBn = SB ^ NEG;

    // ---------- 6 variational layers (tangent form; cos deferred) ----------
#pragma unroll 1
    for (int d = 0; d < 6; d++) {
        const float* td = tsh + d * 10;

        // wires 0..4: cross-lane gates (lane bit u = 4-q)
        // bit==0: n0 = a0 - t*a1 ; bit==1: n1 = a1 + t*a0  (x cos deferred)
#pragma unroll
        for (int q = 0; q < 5; q++) {
            const float t = td[q];
            const int u = 4 - q;
            const float te = ((lane >> u) & 1) ? t : -t;
            const u64 tt = pk2(te, te);
#pragma unroll
            for (int i = 0; i < 32; i++) {
                u64 other = __shfl_xor_sync(0xffffffffu, st[i], 1 << u);
                st[i] = fma2(tt, other, st[i]);
            }
        }

        // wires 5..9: in-register gates (local bit v = 9-q)
#pragma unroll
        for (int q = 5; q < 10; q++) {
            const float t = td[q];
            const int v = 9 - q;
            const u64 tt = pk2(t, t), nt = pk2(-t, -t);
#pragma unroll
            for (int w = 0; w < 16; w++) {
                const int i = ((w >> v) << (v + 1)) | (w & ((1 << v) - 1));
                const int j = i | (1 << v);
                u64 a0 = st[i], a1 = st[j];
                st[i] = fma2(nt, a1, a0);   // a0 - t*a1
                st[j] = fma2(tt, a0, a1);   // a1 + t*a0
            }
        }

        // CZ chain as sign-bit XOR; last layer's CZ doesn't affect |amp|^2
        if (d < 5) {
#pragma unroll
            for (int i = 0; i < 32; i++) {
                const u64 m = (i >= 16) ? (ADJ5(i) ? SBn : SB)
                                        : (ADJ5(i) ? SAn : SA);
                st[i] = st[i] ^ m;
            }
        }
    }

    // ---------- probabilities and <Z_q> ----------
    float t_all = 0.0f, tb0 = 0, tb1 = 0, tb2 = 0, tb3 = 0, tb4 = 0;
#pragma unroll
    for (int i = 0; i < 32; i++) {
        float re, im; upk2(st[i], re, im);
        float p = fmaf(im, im, re * re);
        t_all += p;
        if (i & 1)  tb0 += p;
        if (i & 2)  tb1 += p;
        if (i & 4)  tb2 += p;
        if (i & 8)  tb3 += p;
        if (i & 16) tb4 += p;
    }
    float ex[10];
#pragma unroll
    for (int q = 0; q < 5; q++) {
        const int u = 4 - q;
        ex[q] = ((lane >> u) & 1) ? -t_all : t_all;
    }
    ex[5] = t_all - 2.0f * tb4;  // wire 5 -> local bit 4
    ex[6] = t_all - 2.0f * tb3;
    ex[7] = t_all - 2.0f * tb2;
    ex[8] = t_all - 2.0f * tb1;
    ex[9] = t_all - 2.0f * tb0;

#pragma unroll
    for (int m = 16; m >= 1; m >>= 1) {
#pragma unroll
        for (int q = 0; q < 10; q++)
            ex[q] += __shfl_xor_sync(0xffffffffu, ex[q], m);
    }

    // ---------- classifier head: lanes 0..15 emit one class each ----------
    if (lane < 16) {
        float acc = bsh[lane];
#pragma unroll
        for (int q = 0; q < 10; q++)
            acc = fmaf(ex[q], wsh[lane * 10 + q], acc);
        out[elem * 16 + lane] = acc;
    }
}

extern "C" void kernel_launch(void* const* d_in, const int* in_sizes, int n_in,
                              void* d_out, int out_size)
{
    const float* x      = (const float*)d_in[0];  // (B, 10)
    const float* params = (const float*)d_in[1];  // (6, 10)
    const float* w_cls  = (const float*)d_in[2];  // (16, 10)
    const float* b_cls  = (const float*)d_in[3];  // (16,)
    float* out = (float*)d_out;

    const int B = in_sizes[0] / 10;
    const int warps_per_block = 4;
    const int blocks = (B + warps_per_block - 1) / warps_per_block;
    qsim_kernel<<<blocks, warps_per_block * 32>>>(x, params, w_cls, b_cls, out, B);
}

// round 4
// speedup vs baseline: 1.4849x; 1.2446x over previous
#include <cuda_runtime.h>

typedef unsigned long long u64;

// ---- packed f32x2 helpers (Blackwell sm_100a) ----
__device__ __forceinline__ u64 pk2(float lo, float hi) {
    u64 r; asm("mov.b64 %0, {%1, %2};" : "=l"(r) : "f"(lo), "f"(hi)); return r;
}
__device__ __forceinline__ void upk2(u64 v, float& lo, float& hi) {
    asm("mov.b64 {%0, %1}, %2;" : "=f"(lo), "=f"(hi) : "l"(v));
}
__device__ __forceinline__ u64 fma2(u64 a, u64 b, u64 c) {
    u64 r; asm("fma.rn.f32x2 %0, %1, %2, %3;" : "=l"(r) : "l"(a), "l"(b), "l"(c)); return r;
}
__device__ __forceinline__ u64 mul2(u64 a, u64 b) {
    u64 r; asm("mul.rn.f32x2 %0, %1, %2;" : "=l"(r) : "l"(a), "l"(b)); return r;
}

#define PC6(v) ((((v)>>0)&1)+(((v)>>1)&1)+(((v)>>2)&1)+(((v)>>3)&1)+(((v)>>4)&1)+(((v)>>5)&1))
#define ADJ6(v) (PC6((v)&((v)>>1)) & 1)
#define ADJ4(v) (PC6((v)&((v)>>1)&0x7) & 1)

// 10-qubit register: wire w = flat-index bit (9-w).
// Layout: 2 elements per warp. Half-warp h = lane>>4 owns element 2*warp+h.
//   lane bit u (u=0..3, of l=lane&15) -> global bit 6+u -> wire 3-u
//   local bit v (v=0..5)              -> global bit v   -> wire 9-v
// Each thread holds 64 packed (re,im) amplitudes.

__global__ __launch_bounds__(128)
void qsim_kernel(const float* __restrict__ x,
                 const float* __restrict__ params,
                 const float* __restrict__ w_cls,
                 const float* __restrict__ b_cls,
                 float* __restrict__ out, int B)
{
    __shared__ float tsh[64], cwork[64], wsh[160], bsh[16];
    __shared__ float Cprod_sh;
    const int tid = threadIdx.x;
    if (tid < 60) {
        float s, c;
        sincosf(params[tid] * 0.5f, &s, &c);
        tsh[tid] = s / c;       // tan(theta/2)
        cwork[tid] = c;
    }
    for (int k = tid; k < 160; k += 128) wsh[k] = w_cls[k];
    if (tid < 16) bsh[tid] = b_cls[tid];
    __syncthreads();
    if (tid == 0) {
        float p = 1.0f;
        for (int k = 0; k < 60; k++) p *= cwork[k];
        Cprod_sh = p;           // deferred cos product (applied to amplitudes)
    }
    __syncthreads();
    const float Cprod = Cprod_sh;

    const int lane = tid & 31;
    const int l    = lane & 15;           // lane-id within half-warp (4 bits)
    const int half = lane >> 4;
    const int elem = (blockIdx.x * (blockDim.x >> 5) + (tid >> 5)) * 2 + half;
    if (elem >= B) return;

    // ---------- initial product state from RX layer ----------
    float cx[10], sx[10];
#pragma unroll
    for (int q = 0; q < 10; q++) {
        float xv = x[elem * 10 + q];
        sincosf(xv * 0.5f, &sx[q], &cx[q]);
    }
    // product over the 4 lane bits (wires 3..0), deferred-cos folded in
    float lp = Cprod;
#pragma unroll
    for (int u = 0; u < 4; u++)
        lp *= ((l >> u) & 1) ? sx[3 - u] : cx[3 - u];

    // recursive product over 6 local bits: pr[i] = lp * prod_v (bit? s : c)[9-v]
    float pr[64];
    pr[0] = lp;
#pragma unroll
    for (int v = 0; v < 6; v++) {
#pragma unroll
        for (int i = 0; i < 32; i++) {
            if (i < (1 << v)) {
                pr[i | (1 << v)] = pr[i] * sx[9 - v];
                pr[i]            = pr[i] * cx[9 - v];
            }
        }
    }

    // phase (-i)^k, k = popc(l) + popc(i)
    const int pl = __popc(l);
    u64 ph[4];
#pragma unroll
    for (int j = 0; j < 4; j++) {
        int k = (pl + j) & 3;
        float prr = (k == 0) ? 1.0f : ((k == 2) ? -1.0f : 0.0f);
        float pii = (k == 1) ? -1.0f : ((k == 3) ? 1.0f : 0.0f);
        ph[j] = pk2(prr, pii);
    }

    u64 st[64];
#pragma unroll
    for (int i = 0; i < 64; i++)
        st[i] = mul2(pk2(pr[i], pr[i]), ph[PC6(i) & 3]);

    // ---------- CZ sign masks (XOR on sign bits, ALU pipe) ----------
    // flip(b) = ADJ4(l) ^ ADJ6(i) ^ (lanebit0 & localbit5)
    const u64 NEG = 0x8000000080000000ull;
    const int sig_lane = ADJ4(l);
    const int laneb0   = l & 1;                  // global bit 6
    const u64 SA  = sig_lane ? NEG : 0ull;                 // i < 32
    const u64 SB  = (sig_lane ^ laneb0) ? NEG : 0ull;      // i >= 32 (bit5 set)
    const u64 SAn = SA ^ NEG, SBn = SB ^ NEG;

    // ---------- 6 variational layers (tangent form; cos deferred) ----------
#pragma unroll 1
    for (int d = 0; d < 6; d++) {
        const float* td = tsh + d * 10;

        // wires 0..3: cross-lane gates (lane bit u = 3-q); offsets <16 keep
        // the two half-warps independent under the full mask.
#pragma unroll
        for (int q = 0; q < 4; q++) {
            const float t = td[q];
            const int u = 3 - q;
            const float te = ((l >> u) & 1) ? t : -t;
            const u64 tt = pk2(te, te);
#pragma unroll
            for (int i = 0; i < 64; i++) {
                u64 other = __shfl_xor_sync(0xffffffffu, st[i], 1 << u);
                st[i] = fma2(tt, other, st[i]);
            }
        }

        // wires 4..9: in-register gates (local bit v = 9-q)
#pragma unroll
        for (int q = 4; q < 10; q++) {
            const float t = td[q];
            const int v = 9 - q;
            const u64 tt = pk2(t, t), nt = pk2(-t, -t);
#pragma unroll
            for (int w = 0; w < 32; w++) {
                const int i = ((w >> v) << (v + 1)) | (w & ((1 << v) - 1));
                const int j = i | (1 << v);
                u64 a0 = st[i], a1 = st[j];
                st[i] = fma2(nt, a1, a0);   // a0 - t*a1
                st[j] = fma2(tt, a0, a1);   // a1 + t*a0
            }
        }

        // CZ chain as sign-bit XOR; last layer's CZ doesn't affect |amp|^2
        if (d < 5) {
#pragma unroll
            for (int i = 0; i < 64; i++) {
                const u64 m = (i >= 32) ? (ADJ6(i) ? SBn : SB)
                                        : (ADJ6(i) ? SAn : SA);
                st[i] = st[i] ^ m;
            }
        }
    }

    // ---------- probabilities and <Z_q> ----------
    float t_all = 0.0f, tb[6] = {0, 0, 0, 0, 0, 0};
#pragma unroll
    for (int i = 0; i < 64; i++) {
        float re, im; upk2(st[i], re, im);
        float p = fmaf(im, im, re * re);
        t_all += p;
#pragma unroll
        for (int v = 0; v < 6; v++)
            if (i & (1 << v)) tb[v] += p;
    }
    float ex[10];
#pragma unroll
    for (int q = 0; q < 4; q++) {
        const int u = 3 - q;
        ex[q] = ((l >> u) & 1) ? -t_all : t_all;
    }
#pragma unroll
    for (int v = 0; v < 6; v++)
        ex[9 - v] = t_all - 2.0f * tb[v];

    // reduce across the 16 lanes of this element (offsets stay in-half)
#pragma unroll
    for (int m = 8; m >= 1; m >>= 1) {
#pragma unroll
        for (int q = 0; q < 10; q++)
            ex[q] += __shfl_xor_sync(0xffffffffu, ex[q], m);
    }

    // ---------- classifier head: each of 16 lanes emits one class ----------
    {
        float acc = bsh[l];
#pragma unroll
        for (int q = 0; q < 10; q++)
            acc = fmaf(ex[q], wsh[l * 10 + q], acc);
        out[elem * 16 + l] = acc;
    }
}

extern "C" void kernel_launch(void* const* d_in, const int* in_sizes, int n_in,
                              void* d_out, int out_size)
{
    const float* x      = (const float*)d_in[0];  // (B, 10)
    const float* params = (const float*)d_in[1];  // (6, 10)
    const float* w_cls  = (const float*)d_in[2];  // (16, 10)
    const float* b_cls  = (const float*)d_in[3];  // (16,)
    float* out = (float*)d_out;

    const int B = in_sizes[0] / 10;
    const int elems_per_block = 8;                // 4 warps x 2 elements
    const int blocks = (B + elems_per_block - 1) / elems_per_block;
    qsim_kernel<<<blocks, 128>>>(x, params, w_cls, b_cls, out, B);
}

// round 5
// speedup vs baseline: 1.5113x; 1.0178x over previous
#include <cuda_runtime.h>

typedef unsigned long long u64;
typedef unsigned int u32;

// ---- packed f32x2 helpers (Blackwell sm_100a) ----
__device__ __forceinline__ u64 pk2(float lo, float hi) {
    u64 r; asm("mov.b64 %0, {%1, %2};" : "=l"(r) : "f"(lo), "f"(hi)); return r;
}
__device__ __forceinline__ void upk2(u64 v, float& lo, float& hi) {
    asm("mov.b64 {%0, %1}, %2;" : "=f"(lo), "=f"(hi) : "l"(v));
}
__device__ __forceinline__ u64 fma2(u64 a, u64 b, u64 c) {
    u64 r; asm("fma.rn.f32x2 %0, %1, %2, %3;" : "=l"(r) : "l"(a), "l"(b), "l"(c)); return r;
}
__device__ __forceinline__ u64 dup2(u32 m) {
    u64 r; asm("mov.b64 %0, {%1, %1};" : "=l"(r) : "r"(m)); return r;
}

// 10-qubit register: wire w = flat-index bit (9-w).
// 2 elements per warp; 16 lanes (l = lane&15) per element; 64 amps/thread.
// Slots: 4 lane slots (u=0..3), 6 local slots (v=0..5).
// XOR-skewed storage: register r holds the amp whose local-slot bits are
//   y = r ^ (l & 15)   (bits 0..3 skewed by lane bits; bits 4,5 unskewed)
// Wire assignment alternates per layer (parity p):
//   p=0: lane slot u <-> global bit 6+u ; local slot v <-> global bit v
//   p=1: lane slot u <-> global bit u   ; local slot v<4 <-> bit 6+v ; slots 4,5 <-> bits 4,5
// Swap(lane j <-> local j) in this skew = plain shfl_xor(1<<j) on regs with bit j set.

__global__ __launch_bounds__(128)
void qsim_kernel(const float* __restrict__ x,
                 const float* __restrict__ params,
                 const float* __restrict__ w_cls,
                 const float* __restrict__ b_cls,
                 float* __restrict__ out, int B)
{
    __shared__ float tsh[64], cwork[64], T2[64], wsh[160], bsh[16];
    __shared__ float Cprod_sh;
    const int tid = threadIdx.x;
    if (tid < 60) {
        float s, c;
        sincosf(params[tid] * 0.5f, &s, &c);
        tsh[tid] = s / c;          // tan(theta/2)
        cwork[tid] = c;
    }
    for (int k = tid; k < 160; k += 128) wsh[k] = w_cls[k];
    if (tid < 16) bsh[tid] = b_cls[tid];
    __syncthreads();
    // reorder thetas into per-layer gate order: k=0..5 phase-1 slots, k=6..9 phase-2 slots
    if (tid < 60) {
        int d = tid / 10, k = tid % 10, p = d & 1;
        int wire;
        if (k < 6) wire = p ? ((k < 4) ? 3 - k : 9 - k) : 9 - k;
        else { int j = k - 6; wire = p ? 9 - j : 3 - j; }
        T2[tid] = tsh[d * 10 + wire];
    }
    if (tid == 0) {
        float pp = 1.0f;
        for (int k = 0; k < 60; k++) pp *= cwork[k];
        Cprod_sh = pp;             // deferred cos product
    }
    __syncthreads();
    const float Cprod = Cprod_sh;

    const int lane = tid & 31;
    const int l    = lane & 15;
    const int half = lane >> 4;
    const int elem = (blockIdx.x * (blockDim.x >> 5) + (tid >> 5)) * 2 + half;
    if (elem >= B) return;

    // ---------- initial product state from RX layer (parity 0, skewed) ----------
    float cx[10], sx[10];
#pragma unroll
    for (int q = 0; q < 10; q++) {
        float xv = x[elem * 10 + q];
        sincosf(xv * 0.5f, &sx[q], &cx[q]);
    }
    // lane product: lane slot u <-> bit 6+u <-> wire 3-u
    float lp = Cprod;
#pragma unroll
    for (int u = 0; u < 4; u++)
        lp *= ((l >> u) & 1) ? sx[3 - u] : cx[3 - u];

    // skew-aware per-level factors: reg bit v=1 means amp bit y_v = 1^l_v (v<4)
    float fhi[6], flo[6];
#pragma unroll
    for (int v = 0; v < 4; v++) {
        const bool lb = (l >> v) & 1;
        fhi[v] = lb ? cx[9 - v] : sx[9 - v];
        flo[v] = lb ? sx[9 - v] : cx[9 - v];
    }
    fhi[4] = sx[5]; flo[4] = cx[5];
    fhi[5] = sx[4]; flo[5] = cx[4];

    float pr[64];
    pr[0] = lp;
#pragma unroll
    for (int v = 0; v < 6; v++) {
#pragma unroll
        for (int i = 0; i < 32; i++) {
            if (i < (1 << v)) {
                pr[i | (1 << v)] = pr[i] * fhi[v];
                pr[i]            = pr[i] * flo[v];
            }
        }
    }

    // phase (-i)^popc(b): parity of popc splits; 2E-term via per-thread bit table
    // Tpar bit r15 = parity(r15 & l); fold in popc(l)&1
    u32 Tpar = 0;
    if (l & 1) Tpar ^= 0xAAAAu;
    if (l & 2) Tpar ^= 0xCCCCu;
    if (l & 4) Tpar ^= 0xF0F0u;
    if (l & 8) Tpar ^= 0xFF00u;
    if (__popc(l) & 1) Tpar ^= 0xFFFFu;

    u64 st[64];
#pragma unroll
    for (int r = 0; r < 64; r++) {
        const int C = __popc(r);                       // compile-time
        const u32 e31 = ((Tpar >> (r & 15)) & 1u) << 31;
        const u32 bits = __float_as_uint(pr[r]);
        if ((C & 1) == 0) {
            const u32 reb = bits ^ e31 ^ ((u32)((C >> 1) & 1) << 31);
            st[r] = pk2(__uint_as_float(reb), 0.0f);
        } else {
            const u32 imb = bits ^ e31 ^ ((u32)(((C >> 1) & 1) ^ 1) << 31);
            st[r] = pk2(0.0f, __uint_as_float(imb));
        }
    }

    // ---------- CZ flip tables (16-bit words indexed by r&15) ----------
    // K_ADJ4 bit y = ADJ4(y); xor-permute by l so index becomes r15.
    u32 A = 0xB848u;
    if (l & 1) A = ((A & 0x5555u) << 1) | ((A & 0xAAAAu) >> 1);
    if (l & 2) A = ((A & 0x3333u) << 2) | ((A & 0xCCCCu) >> 2);
    if (l & 4) A = ((A & 0x0F0Fu) << 4) | ((A & 0xF0F0u) >> 4);
    if (l & 8) A = ((A & 0x00FFu) << 8) | ((A & 0xFF00u) >> 8);
    const u32 adjl = (__popc(l & (l >> 1)) & 1) ? 0xFFFFu : 0u;
    const u32 base = A ^ adjl;
    const u32 Y0 = (l & 1) ? 0x5555u : 0xAAAAu;   // r-bits where y0=1
    const u32 Y3 = (l & 8) ? 0x00FFu : 0xFF00u;   // r-bits where y3=1
    const u32 L3 = (l & 8) ? 0xFFFFu : 0u;
    const u32 L0 = (l & 1) ? 0xFFFFu : 0u;
    // parity-1 exit: flip = ADJ4(l) ^ l3*r4 ^ r4*r5 ^ r5*y0 ^ ADJ4(y)
    const u32 W1_00 = base;
    const u32 W1_10 = base ^ L3;
    const u32 W1_01 = base ^ Y0;
    const u32 W1_11 = base ^ L3 ^ 0xFFFFu ^ Y0;
    // parity-0 exit: flip = ADJ4(y) ^ y3*r4 ^ r4*r5 ^ r5*l0 ^ ADJ4(l)
    const u32 W0_00 = base;
    const u32 W0_10 = base ^ Y3;
    const u32 W0_01 = base ^ L0;
    const u32 W0_11 = base ^ Y3 ^ 0xFFFFu ^ L0;

    // ---------- 6 variational layers ----------
#pragma unroll 1
    for (int d = 0; d < 6; d++) {
        const int p = d & 1;

        // phase 1: gate the 6 wires on local slots (slots 0-3 skew-signed)
#pragma unroll
        for (int k = 0; k < 6; k++) {
            const float t = T2[d * 10 + k];
            float te = t;
            if (k < 4) te = ((l >> k) & 1) ? -t : t;
            const u64 tt = pk2(te, te), nt = pk2(-te, -te);
#pragma unroll
            for (int w = 0; w < 32; w++) {
                const int i  = ((w >> k) << (k + 1)) | (w & ((1 << k) - 1));
                const int j2 = i | (1 << k);
                const u64 a0 = st[i], a1 = st[j2];
                st[i]  = fma2(nt, a1, a0);   // a0 - te*a1
                st[j2] = fma2(tt, a0, a1);   // a1 + te*a0
            }
        }

        // swaps: lane slot j <-> local slot j  (clean shfl, no fixups)
#pragma unroll
        for (int j = 0; j < 4; j++) {
#pragma unroll
            for (int r = 0; r < 64; r++)
                if (r & (1 << j))
                    st[r] = __shfl_xor_sync(0xffffffffu, st[r], 1 << j);
        }

        // phase 2: gate the 4 wires that just arrived in local slots 0-3
#pragma unroll
        for (int k = 0; k < 4; k++) {
            const float t = T2[d * 10 + 6 + k];
            const float te = ((l >> k) & 1) ? -t : t;
            const u64 tt = pk2(te, te), nt = pk2(-te, -te);
#pragma unroll
            for (int w = 0; w < 32; w++) {
                const int i  = ((w >> k) << (k + 1)) | (w & ((1 << k) - 1));
                const int j2 = i | (1 << k);
                const u64 a0 = st[i], a1 = st[j2];
                st[i]  = fma2(nt, a1, a0);
                st[j2] = fma2(tt, a0, a1);
            }
        }

        // CZ chain (diagonal): sign-bit XOR from per-thread tables; skip last
        if (d < 5) {
            const int q = p ^ 1;   // exit parity
            const u32 Wa = q ? W1_00 : W0_00;
            const u32 Wb = q ? W1_10 : W0_10;
            const u32 Wc = q ? W1_01 : W0_01;
            const u32 Wd = q ? W1_11 : W0_11;
#pragma unroll
            for (int r = 0; r < 64; r++) {
                const u32 W = ((r >> 4) & 1) ? (((r >> 5) & 1) ? Wd : Wb)
                                             : (((r >> 5) & 1) ? Wc : Wa);
                const u32 m = (W << (31 - (r & 15))) & 0x80000000u;
                st[r] ^= dup2(m);
            }
        }
    }

    // ---------- probabilities and <Z_q> (final layout = parity 0, skewed) ----------
    float t_all = 0.0f, tb[6] = {0, 0, 0, 0, 0, 0};
#pragma unroll
    for (int r = 0; r < 64; r++) {
        float re, im; upk2(st[r], re, im);
        const float p2 = fmaf(im, im, re * re);
        t_all += p2;
#pragma unroll
        for (int v = 0; v < 6; v++)
            if (r & (1 << v)) tb[v] += p2;
    }
    float ex[10];
#pragma unroll
    for (int q2 = 0; q2 < 4; q2++)                    // lane slots: bit 6+u -> wire 3-u
        ex[q2] = ((l >> (3 - q2)) & 1) ? -t_all : t_all;
#pragma unroll
    for (int v = 0; v < 4; v++) {                     // skewed local slots: bit v -> wire 9-v
        const float e = t_all - 2.0f * tb[v];
        ex[9 - v] = ((l >> v) & 1) ? -e : e;
    }
    ex[5] = t_all - 2.0f * tb[4];                     // bit 4 -> wire 5
    ex[4] = t_all - 2.0f * tb[5];                     // bit 5 -> wire 4

    // reduce across the 16 lanes of this element
#pragma unroll
    for (int m = 8; m >= 1; m >>= 1) {
#pragma unroll
        for (int q2 = 0; q2 < 10; q2++)
            ex[q2] += __shfl_xor_sync(0xffffffffu, ex[q2], m);
    }

    // ---------- classifier head: each of 16 lanes emits one class ----------
    {
        float acc = bsh[l];
#pragma unroll
        for (int q2 = 0; q2 < 10; q2++)
            acc = fmaf(ex[q2], wsh[l * 10 + q2], acc);
        out[elem * 16 + l] = acc;
    }
}

extern "C" void kernel_launch(void* const* d_in, const int* in_sizes, int n_in,
                              void* d_out, int out_size)
{
    const float* x      = (const float*)d_in[0];  // (B, 10)
    const float* params = (const float*)d_in[1];  // (6, 10)
    const float* w_cls  = (const float*)d_in[2];  // (16, 10)
    const float* b_cls  = (const float*)d_in[3];  // (16,)
    float* out = (float*)d_out;

    const int B = in_sizes[0] / 10;
    const int elems_per_block = 8;                // 4 warps x 2 elements
    const int blocks = (B + elems_per_block - 1) / elems_per_block;
    qsim_kernel<<<blocks, 128>>>(x, params, w_cls, b_cls, out, B);
}

// round 6
// speedup vs baseline: 1.6535x; 1.0941x over previous
#include <cuda_runtime.h>

typedef unsigned long long u64;
typedef unsigned int u32;

// ---- packed f32x2 helpers (Blackwell sm_100a) ----
__device__ __forceinline__ u64 pk2(float lo, float hi) {
    u64 r; asm("mov.b64 %0, {%1, %2};" : "=l"(r) : "f"(lo), "f"(hi)); return r;
}
__device__ __forceinline__ void upk2(u64 v, float& lo, float& hi) {
    asm("mov.b64 {%0, %1}, %2;" : "=f"(lo), "=f"(hi) : "l"(v));
}
__device__ __forceinline__ u64 fma2(u64 a, u64 b, u64 c) {
    u64 r; asm("fma.rn.f32x2 %0, %1, %2, %3;" : "=l"(r) : "l"(a), "l"(b), "l"(c)); return r;
}
__device__ __forceinline__ u64 dup2(u32 m) {
    u64 r; asm("mov.b64 %0, {%1, %1};" : "=l"(r) : "r"(m)); return r;
}

// 10-qubit register: wire w = flat-index bit (9-w).
// 2 elements per warp; 16 lanes (l = lane&15) per element; 64 amps/thread.
// XOR-skewed storage: register r holds the amp whose local-slot bits are
//   y = r ^ (l & 15)   (bits 0..3 skewed by lane bits; bits 4,5 unskewed)
// Wire assignment alternates per layer (parity p):
//   p=0: lane slot u <-> global bit 6+u ; local slot v <-> global bit v
//   p=1: lane slot u <-> global bit u   ; local slot v<4 <-> bit 6+v ; slots 4,5 <-> bits 4,5
// Swap(lane j <-> local j) in this skew = plain shfl_xor(1<<j) on regs with bit j set.

__global__ __launch_bounds__(128, 3)
void qsim_kernel(const float* __restrict__ x,
                 const float* __restrict__ params,
                 const float* __restrict__ w_cls,
                 const float* __restrict__ b_cls,
                 float* __restrict__ out, int B)
{
    __shared__ float tsh[64], cwork[64], T2[64], wsh[160], bsh[16];
    __shared__ float Cprod_sh;
    const int tid = threadIdx.x;
    if (tid < 60) {
        float s, c;
        sincosf(params[tid] * 0.5f, &s, &c);
        tsh[tid] = s / c;          // tan(theta/2)
        cwork[tid] = c;
    }
    for (int k = tid; k < 160; k += 128) wsh[k] = w_cls[k];
    if (tid < 16) bsh[tid] = b_cls[tid];
    __syncthreads();
    // reorder thetas into per-layer gate order: k=0..5 phase-1 slots, k=6..9 phase-2 slots
    if (tid < 60) {
        int d = tid / 10, k = tid % 10, p = d & 1;
        int wire;
        if (k < 6) wire = p ? ((k < 4) ? 3 - k : 9 - k) : 9 - k;
        else { int j = k - 6; wire = p ? 9 - j : 3 - j; }
        T2[tid] = tsh[d * 10 + wire];
    }
    if (tid == 0) {
        float pp = 1.0f;
        for (int k = 0; k < 60; k++) pp *= cwork[k];
        Cprod_sh = pp;             // deferred cos product
    }
    __syncthreads();
    const float Cprod = Cprod_sh;

    const int lane = tid & 31;
    const int l    = lane & 15;
    const int half = lane >> 4;
    const int elem = (blockIdx.x * (blockDim.x >> 5) + (tid >> 5)) * 2 + half;
    if (elem >= B) return;

    // ---------- initial product state from RX layer (parity 0, skewed) ----------
    float cx[10], sx[10];
#pragma unroll
    for (int q = 0; q < 10; q++) {
        float xv = x[elem * 10 + q];
        sincosf(xv * 0.5f, &sx[q], &cx[q]);
    }
    // lane product: lane slot u <-> bit 6+u <-> wire 3-u
    float lp = Cprod;
#pragma unroll
    for (int u = 0; u < 4; u++)
        lp *= ((l >> u) & 1) ? sx[3 - u] : cx[3 - u];

    // skew-aware per-level factors: reg bit v=1 means amp bit y_v = 1^l_v (v<4)
    float fhi[6], flo[6];
#pragma unroll
    for (int v = 0; v < 4; v++) {
        const bool lb = (l >> v) & 1;
        fhi[v] = lb ? cx[9 - v] : sx[9 - v];
        flo[v] = lb ? sx[9 - v] : cx[9 - v];
    }
    fhi[4] = sx[5]; flo[4] = cx[5];
    fhi[5] = sx[4]; flo[5] = cx[4];

    float pr[64];
    pr[0] = lp;
#pragma unroll
    for (int v = 0; v < 6; v++) {
#pragma unroll
        for (int i = 0; i < 32; i++) {
            if (i < (1 << v)) {
                pr[i | (1 << v)] = pr[i] * fhi[v];
                pr[i]            = pr[i] * flo[v];
            }
        }
    }

    // phase (-i)^popc(b): parity of popc splits; 2E-term via per-thread bit table
    u32 Tpar = 0;
    if (l & 1) Tpar ^= 0xAAAAu;
    if (l & 2) Tpar ^= 0xCCCCu;
    if (l & 4) Tpar ^= 0xF0F0u;
    if (l & 8) Tpar ^= 0xFF00u;
    if (__popc(l) & 1) Tpar ^= 0xFFFFu;

    u64 st[64];
#pragma unroll
    for (int r = 0; r < 64; r++) {
        const int C = __popc(r);                       // compile-time
        const u32 e31 = ((Tpar >> (r & 15)) & 1u) << 31;
        const u32 bits = __float_as_uint(pr[r]);
        if ((C & 1) == 0) {
            const u32 reb = bits ^ e31 ^ ((u32)((C >> 1) & 1) << 31);
            st[r] = pk2(__uint_as_float(reb), 0.0f);
        } else {
            const u32 imb = bits ^ e31 ^ ((u32)(((C >> 1) & 1) ^ 1) << 31);
            st[r] = pk2(0.0f, __uint_as_float(imb));
        }
    }

    // ---------- CZ flip tables (16-bit words indexed by r&15) ----------
    u32 A = 0xB848u;
    if (l & 1) A = ((A & 0x5555u) << 1) | ((A & 0xAAAAu) >> 1);
    if (l & 2) A = ((A & 0x3333u) << 2) | ((A & 0xCCCCu) >> 2);
    if (l & 4) A = ((A & 0x0F0Fu) << 4) | ((A & 0xF0F0u) >> 4);
    if (l & 8) A = ((A & 0x00FFu) << 8) | ((A & 0xFF00u) >> 8);
    const u32 adjl = (__popc(l & (l >> 1)) & 1) ? 0xFFFFu : 0u;
    const u32 base = A ^ adjl;
    const u32 Y0 = (l & 1) ? 0x5555u : 0xAAAAu;   // r-bits where y0=1
    const u32 Y3 = (l & 8) ? 0x00FFu : 0xFF00u;   // r-bits where y3=1
    const u32 L3 = (l & 8) ? 0xFFFFu : 0u;
    const u32 L0 = (l & 1) ? 0xFFFFu : 0u;
    // parity-1 exit: flip = ADJ4(l) ^ l3*r4 ^ r4*r5 ^ r5*y0 ^ ADJ4(y)
    const u32 W1_00 = base;
    const u32 W1_10 = base ^ L3;
    const u32 W1_01 = base ^ Y0;
    const u32 W1_11 = base ^ L3 ^ 0xFFFFu ^ Y0;
    // parity-0 exit: flip = ADJ4(y) ^ y3*r4 ^ r4*r5 ^ r5*l0 ^ ADJ4(l)
    const u32 W0_00 = base;
    const u32 W0_10 = base ^ Y3;
    const u32 W0_01 = base ^ L0;
    const u32 W0_11 = base ^ Y3 ^ 0xFFFFu ^ L0;

    // ---------- 6 variational layers ----------
#pragma unroll 1
    for (int d = 0; d < 6; d++) {
        const int p = d & 1;

        // phase 1: gate the 6 wires on local slots (slots 0-3 skew-signed)
#pragma unroll
        for (int k = 0; k < 6; k++) {
            const float t = T2[d * 10 + k];
            float te = t;
            if (k < 4) te = ((l >> k) & 1) ? -t : t;
            const u64 tt = pk2(te, te), nt = pk2(-te, -te);
#pragma unroll
            for (int w = 0; w < 32; w++) {
                const int i  = ((w >> k) << (k + 1)) | (w & ((1 << k) - 1));
                const int j2 = i | (1 << k);
                const u64 a0 = st[i], a1 = st[j2];
                st[i]  = fma2(nt, a1, a0);   // a0 - te*a1
                st[j2] = fma2(tt, a0, a1);   // a1 + te*a0
            }
        }

        // swaps: lane slot j <-> local slot j  (clean shfl, no fixups)
#pragma unroll
        for (int j = 0; j < 4; j++) {
#pragma unroll
            for (int r = 0; r < 64; r++)
                if (r & (1 << j))
                    st[r] = __shfl_xor_sync(0xffffffffu, st[r], 1 << j);
        }

        // phase 2: gate the 4 wires that just arrived in local slots 0-3
#pragma unroll
        for (int k = 0; k < 4; k++) {
            const float t = T2[d * 10 + 6 + k];
            const float te = ((l >> k) & 1) ? -t : t;
            const u64 tt = pk2(te, te), nt = pk2(-te, -te);
#pragma unroll
            for (int w = 0; w < 32; w++) {
                const int i  = ((w >> k) << (k + 1)) | (w & ((1 << k) - 1));
                const int j2 = i | (1 << k);
                const u64 a0 = st[i], a1 = st[j2];
                st[i]  = fma2(nt, a1, a0);
                st[j2] = fma2(tt, a0, a1);
            }
        }

        // CZ chain (diagonal): sign-bit XOR from per-thread tables; skip last
        if (d < 5) {
            const int q = p ^ 1;   // exit parity
            const u32 Wa = q ? W1_00 : W0_00;
            const u32 Wb = q ? W1_10 : W0_10;
            const u32 Wc = q ? W1_01 : W0_01;
            const u32 Wd = q ? W1_11 : W0_11;
#pragma unroll
            for (int r = 0; r < 64; r++) {
                const u32 W = ((r >> 4) & 1) ? (((r >> 5) & 1) ? Wd : Wb)
                                             : (((r >> 5) & 1) ? Wc : Wa);
                const u32 m = (W << (31 - (r & 15))) & 0x80000000u;
                st[r] ^= dup2(m);
            }
        }
    }

    // ---------- probabilities and <Z_q> (final layout = parity 0, skewed) ----------
    float t_all = 0.0f, tb[6] = {0, 0, 0, 0, 0, 0};
#pragma unroll
    for (int r = 0; r < 64; r++) {
        float re, im; upk2(st[r], re, im);
        const float p2 = fmaf(im, im, re * re);
        t_all += p2;
#pragma unroll
        for (int v = 0; v < 6; v++)
            if (r & (1 << v)) tb[v] += p2;
    }
    float ex[10];
#pragma unroll
    for (int q2 = 0; q2 < 4; q2++)                    // lane slots: bit 6+u -> wire 3-u
        ex[q2] = ((l >> (3 - q2)) & 1) ? -t_all : t_all;
#pragma unroll
    for (int v = 0; v < 4; v++) {                     // skewed local slots: bit v -> wire 9-v
        const float e = t_all - 2.0f * tb[v];
        ex[9 - v] = ((l >> v) & 1) ? -e : e;
    }
    ex[5] = t_all - 2.0f * tb[4];                     // bit 4 -> wire 5
    ex[4] = t_all - 2.0f * tb[5];                     // bit 5 -> wire 4

    // reduce across the 16 lanes of this element
#pragma unroll
    for (int m = 8; m >= 1; m >>= 1) {
#pragma unroll
        for (int q2 = 0; q2 < 10; q2++)
            ex[q2] += __shfl_xor_sync(0xffffffffu, ex[q2], m);
    }

    // ---------- classifier head: each of 16 lanes emits one class ----------
    {
        float acc = bsh[l];
#pragma unroll
        for (int q2 = 0; q2 < 10; q2++)
            acc = fmaf(ex[q2], wsh[l * 10 + q2], acc);
        out[elem * 16 + l] = acc;
    }
}

extern "C" void kernel_launch(void* const* d_in, const int* in_sizes, int n_in,
                              void* d_out, int out_size)
{
    const float* x      = (const float*)d_in[0];  // (B, 10)
    const float* params = (const float*)d_in[1];  // (6, 10)
    const float* w_cls  = (const float*)d_in[2];  // (16, 10)
    const float* b_cls  = (const float*)d_in[3];  // (16,)
    float* out = (float*)d_out;

    const int B = in_sizes[0] / 10;
    const int elems_per_block = 8;                // 4 warps x 2 elements
    const int blocks = (B + elems_per_block - 1) / elems_per_block;
    qsim_kernel<<<blocks, 128>>>(x, params, w_cls, b_cls, out, B);
}